// round 15
// baseline (speedup 1.0000x reference)
#include <cuda_runtime.h>
#include <stdint.h>

#define KTAPS 27
#define SELF_K 13        // (0,0,0) offset: pair_in == row, mask == 1 always
#define CCH 64
#define THREADS 256
#define MAXN 1048576     // scratch capacity (rows)
#define SPARSE_BLOCKS 1024

#define F32_ONE   0x3F800000u

// Worklist of rows with >=1 neighbor tap. Order is non-deterministic (atomic
// append), but each entry is processed independently with fixed per-row FP
// order -> output deterministic.
__device__ unsigned g_wl_rows[MAXN];
__device__ uint4    g_wl_info[MAXN];   // {bits, j0, j1, j2}
__device__ unsigned g_wl_count;        // reset by ksparse's last block
__device__ unsigned g_done;

// ---------------- kbits: mask scan + worklist compaction ----------------
// Inline width detection from fixed self-tap words (all blocks read the same
// values -> identical decision, deterministic).
__global__ __launch_bounds__(256)
void kbits(const void* __restrict__ maskp, const void* __restrict__ pinp, int n)
{
    const unsigned* m32 = (const unsigned*)maskp;
    const unsigned w = __ldg(m32 + (size_t)SELF_K * (size_t)n);
    int mk = 0;                                   // 0 = 4-byte mask elements
    if (w != 1u && w != F32_ONE) {
        const unsigned w2 = __ldg(m32 + ((size_t)SELF_K * (size_t)n) / 2);
        if ((w2 & 0xFFFFu) == 0x3F80u) mk = 1;    // 1 = 2-byte (bf16) mask
    }
    const int* p32 = (const int*)pinp;
    const bool pw4 = (__ldg(p32 + (size_t)SELF_K * (size_t)n + 1) == 1) &&
                     (__ldg(p32 + (size_t)SELF_K * (size_t)n + 2) == 2);

    const int row = blockIdx.x * 256 + threadIdx.x;

    unsigned bits = 0u;
    if (row < n) {
        if (mk == 0) {
            #pragma unroll
            for (int kk = 0; kk < 26; kk++) {
                const int k = kk + (kk >= SELF_K);
                if (__ldcs(m32 + (size_t)k * (size_t)n + row)) bits |= 1u << k;
            }
        } else {
            const unsigned short* m16 = (const unsigned short*)maskp;
            #pragma unroll
            for (int kk = 0; kk < 26; kk++) {
                const int k = kk + (kk >= SELF_K);
                if (__ldcs(m16 + (size_t)k * (size_t)n + row)) bits |= 1u << k;
            }
        }
    }

    // Fetch pair_in for the first <=3 set neighbor taps (ascending k).
    unsigned j0 = 0, j1 = 0, j2 = 0;
    unsigned bb = bits;
    int cnt = 0;
    while (bb && cnt < 3) {
        const int k = __ffs(bb) - 1;
        bb &= bb - 1;
        const unsigned j = pw4
            ? (unsigned)__ldg(p32 + (size_t)k * (size_t)n + row)
            : (unsigned)__ldg((const long long*)pinp + (size_t)k * (size_t)n + row);
        if (cnt == 0) j0 = j; else if (cnt == 1) j1 = j; else j2 = j;
        cnt++;
    }

    // Warp-aggregated worklist append.
    const bool active = (bits != 0u);
    const unsigned m = __ballot_sync(0xFFFFFFFFu, active);
    if (m) {
        const int lane   = threadIdx.x & 31;
        const int leader = __ffs(m) - 1;
        unsigned base = 0;
        if (lane == leader) base = atomicAdd(&g_wl_count, (unsigned)__popc(m));
        base = __shfl_sync(0xFFFFFFFFu, base, leader);
        if (active) {
            const unsigned slot = base + (unsigned)__popc(m & ((1u << lane) - 1u));
            g_wl_rows[slot] = (unsigned)row;
            g_wl_info[slot] = make_uint4(bits, j0, j1, j2);
        }
    }
}

// ---------------- kdense: out = bias + w13 * features (pure streaming) ----------------
__global__ __launch_bounds__(THREADS)
void kdense(const float* __restrict__ features,
            const float* __restrict__ weight,
            const float* __restrict__ bias,
            float* __restrict__ out,
            int n16)                      // n * 16 float4 elements
{
    const int idx = blockIdx.x * THREADS + threadIdx.x;
    if (idx >= n16) return;
    const int c4 = idx & 15;
    const float4 fv = reinterpret_cast<const float4*>(features)[idx];
    const float4 wv = __ldg(reinterpret_cast<const float4*>(weight) + SELF_K * 16 + c4);
    const float4 bv = __ldg(reinterpret_cast<const float4*>(bias) + c4);
    float4 o;
    o.x = fmaf(fv.x, wv.x, bv.x);
    o.y = fmaf(fv.y, wv.y, bv.y);
    o.z = fmaf(fv.z, wv.z, bv.z);
    o.w = fmaf(fv.w, wv.w, bv.w);
    reinterpret_cast<float4*>(out)[idx] = o;   // default store: ksparse re-reads some rows
}

// ---------------- ksparse: neighbor corrections on the worklist ----------------
__global__ __launch_bounds__(THREADS)
void ksparse(const float* __restrict__ features,
             const float* __restrict__ weight,
             const void* __restrict__ pinp,    // overflow taps (>3) only
             float* __restrict__ out,
             int n)
{
    const int* p32 = (const int*)pinp;
    const bool pw4 = (__ldg(p32 + (size_t)SELF_K * (size_t)n + 1) == 1) &&
                     (__ldg(p32 + (size_t)SELF_K * (size_t)n + 2) == 2);

    const unsigned total = g_wl_count;
    const int t  = threadIdx.x;
    const int r  = t >> 4;        // entry within block-slice (0..15)
    const int c4 = t & 15;

    for (unsigned e = blockIdx.x * 16u + (unsigned)r; e < total;
         e += (unsigned)gridDim.x * 16u) {
        const unsigned row  = g_wl_rows[e];
        const uint4    info = g_wl_info[e];

        float4 acc = reinterpret_cast<const float4*>(out)[(size_t)row * 16 + c4];

        unsigned b = info.x;
        int cnt = 0;
        while (b) {
            const int k = __ffs(b) - 1;
            b &= b - 1;
            int j;
            if      (cnt == 0) j = (int)info.y;
            else if (cnt == 1) j = (int)info.z;
            else if (cnt == 2) j = (int)info.w;
            else j = pw4 ? __ldg(p32 + (size_t)k * (size_t)n + row)
                         : (int)__ldg((const long long*)pinp + (size_t)k * (size_t)n + row);
            cnt++;
            const float4 fv = reinterpret_cast<const float4*>(features)[(size_t)j * 16 + c4];
            const float4 wv = __ldg(reinterpret_cast<const float4*>(weight) + k * 16 + c4);
            acc.x = fmaf(fv.x, wv.x, acc.x);
            acc.y = fmaf(fv.y, wv.y, acc.y);
            acc.z = fmaf(fv.z, wv.z, acc.z);
            acc.w = fmaf(fv.w, wv.w, acc.w);
        }

        reinterpret_cast<float4*>(out)[(size_t)row * 16 + c4] = acc;
    }

    // Last-finishing block resets the worklist for the next graph replay.
    __syncthreads();
    __shared__ unsigned is_last;
    if (t == 0) {
        __threadfence();
        is_last = (atomicAdd(&g_done, 1u) == gridDim.x - 1u);
    }
    __syncthreads();
    if (is_last && t == 0) {
        g_wl_count = 0u;
        g_done = 0u;
        __threadfence();
    }
}

extern "C" void kernel_launch(void* const* d_in, const int* in_sizes, int n_in,
                              void* d_out, int out_size)
{
    // Inputs in metadata order: features, weight, bias, pair_in, pair_out,
    // pair_mask. Identify by element count; the three 27*N arrays keep their
    // metadata order (pair_in, pair_out, pair_mask).
    int fi = -1, wi = -1, bi = -1;
    int big[3], nbig = 0;
    long long maxc = -1;
    for (int i = 0; i < n_in; i++)
        if ((long long)in_sizes[i] > maxc) { maxc = in_sizes[i]; fi = i; }
    for (int i = 0; i < n_in; i++) {
        if (i == fi) continue;
        if (in_sizes[i] == 64) bi = i;
        else if (in_sizes[i] == KTAPS * CCH) wi = i;
        else if (nbig < 3) big[nbig++] = i;
    }
    const float* features = (const float*)d_in[fi];
    const float* weight   = (const float*)d_in[wi];
    const float* bias     = (const float*)d_in[bi];
    const void*  pinp     = d_in[big[0]];   // pair_in
    // big[1] = pair_out (unused: scatter target == row under mask)
    const void*  maskp    = d_in[big[2]];   // pair_mask
    float* out = (float*)d_out;

    const int n = in_sizes[fi] / CCH;
    const int n16 = n * 16;

    kbits<<<(n + 255) / 256, 256>>>(maskp, pinp, n);
    kdense<<<(n16 + THREADS - 1) / THREADS, THREADS>>>(features, weight, bias, out, n16);
    ksparse<<<SPARSE_BLOCKS, THREADS>>>(features, weight, pinp, out, n);
}

// round 16
// speedup vs baseline: 1.2093x; 1.2093x over previous
#include <cuda_runtime.h>
#include <stdint.h>

#define KTAPS 27
#define SELF_K 13        // (0,0,0) offset: pair_in == row, mask == 1 always
#define CCH 64
#define TILE 16          // rows per tile in main kernel
#define THREADS 256
#define MAXN 1048576     // scratch capacity (rows)
#define MAIN_BLOCKS 1184 // ~8 resident blocks per SM (148 SMs)

#define F32_ONE   0x3F800000u

// Per-row packed info: {neighbor bits (bit13 unused), j0, j1, j2} where
// j0..j2 are pair_in indices of the first (ascending k) set neighbor taps.
__device__ uint4 g_info[MAXN];

// ---------------- mask -> {bits, j0..j2} precompute (R13, unchanged) ----------------
__global__ __launch_bounds__(256)
void kbits(const void* __restrict__ maskp, const void* __restrict__ pinp, int n)
{
    const unsigned* m32 = (const unsigned*)maskp;
    const unsigned w = __ldg(m32 + (size_t)SELF_K * (size_t)n);
    int mk = 0;                                   // 0 = 4-byte mask elements
    if (w != 1u && w != F32_ONE) {
        const unsigned w2 = __ldg(m32 + ((size_t)SELF_K * (size_t)n) / 2);
        if ((w2 & 0xFFFFu) == 0x3F80u) mk = 1;    // 1 = 2-byte (bf16) mask
    }
    const int* p32 = (const int*)pinp;
    const bool pw4 = (__ldg(p32 + (size_t)SELF_K * (size_t)n + 1) == 1) &&
                     (__ldg(p32 + (size_t)SELF_K * (size_t)n + 2) == 2);

    const int row = blockIdx.x * 256 + threadIdx.x;
    if (row >= n) return;

    unsigned bits = 0u;
    if (mk == 0) {
        #pragma unroll
        for (int kk = 0; kk < 26; kk++) {
            const int k = kk + (kk >= SELF_K);
            if (__ldcs(m32 + (size_t)k * (size_t)n + row)) bits |= 1u << k;
        }
    } else {
        const unsigned short* m16 = (const unsigned short*)maskp;
        #pragma unroll
        for (int kk = 0; kk < 26; kk++) {
            const int k = kk + (kk >= SELF_K);
            if (__ldcs(m16 + (size_t)k * (size_t)n + row)) bits |= 1u << k;
        }
    }

    // pair_in for the first <=3 set neighbor taps (ascending k); overflow
    // taps (P ~ 6e-4) are read directly by the main kernel.
    unsigned j0 = 0, j1 = 0, j2 = 0;
    unsigned bb = bits;
    int cnt = 0;
    while (bb && cnt < 3) {
        const int k = __ffs(bb) - 1;
        bb &= bb - 1;
        const unsigned j = pw4
            ? (unsigned)__ldg(p32 + (size_t)k * (size_t)n + row)
            : (unsigned)__ldg((const long long*)pinp + (size_t)k * (size_t)n + row);
        if (cnt == 0) j0 = j; else if (cnt == 1) j1 = j; else j2 = j;
        cnt++;
    }
    g_info[row] = make_uint4(bits, j0, j1, j2);
}

// ---------------- main kernel: persistent + 2-stage software pipeline ----------------
__global__ __launch_bounds__(THREADS)
void spdwconv_kernel(const float* __restrict__ features,
                     const float* __restrict__ weight,   // [27*64], L1-resident
                     const float* __restrict__ bias,     // [64]
                     const void* __restrict__ pinp,      // pair_in (overflow only)
                     float* __restrict__ out,
                     int n)
{
    const int* p32 = (const int*)pinp;
    const bool pw4 = (__ldg(p32 + (size_t)SELF_K * (size_t)n + 1) == 1) &&
                     (__ldg(p32 + (size_t)SELF_K * (size_t)n + 2) == 2);

    const int t  = threadIdx.x;
    const int r  = t >> 4;        // row within tile (0..15)
    const int c4 = t & 15;        // float4 channel group
    const int ntiles = (n + TILE - 1) / TILE;

    const float4 bv  = __ldg(reinterpret_cast<const float4*>(bias) + c4);
    const float4 w13 = __ldg(reinterpret_cast<const float4*>(weight) + SELF_K * 16 + c4);

    int tile = blockIdx.x;
    if (tile >= ntiles) return;

    // Stage 0: prologue loads for the first tile.
    int  nn = tile * TILE + r;
    bool v  = nn < n;
    uint4  info = v ? g_info[nn] : make_uint4(0, 0, 0, 0);
    float4 fv   = v ? reinterpret_cast<const float4*>(features)[(size_t)nn * 16 + c4]
                    : make_float4(0.f, 0.f, 0.f, 0.f);

    for (;;) {
        // Prefetch next tile's info + self-feature BEFORE consuming current.
        const int  ntile = tile + gridDim.x;
        const bool hn    = ntile < ntiles;
        const int  nn2   = ntile * TILE + r;
        const bool v2    = hn && (nn2 < n);
        uint4  info2 = make_uint4(0, 0, 0, 0);
        float4 fv2   = make_float4(0.f, 0.f, 0.f, 0.f);
        if (v2) {
            info2 = g_info[nn2];
            fv2   = reinterpret_cast<const float4*>(features)[(size_t)nn2 * 16 + c4];
        }

        if (v) {
            float4 acc = bv;
            unsigned blo = info.x & ((1u << SELF_K) - 1u);
            unsigned bhi = info.x >> (SELF_K + 1);
            int cnt = 0;

            // taps 0..12 (ascending, deterministic)
            while (blo) {
                const int k = __ffs(blo) - 1;
                blo &= blo - 1;
                int j;
                if      (cnt == 0) j = (int)info.y;
                else if (cnt == 1) j = (int)info.z;
                else if (cnt == 2) j = (int)info.w;
                else j = pw4 ? __ldg(p32 + (size_t)k * (size_t)n + nn)
                             : (int)__ldg((const long long*)pinp + (size_t)k * (size_t)n + nn);
                cnt++;
                const float4 gv = reinterpret_cast<const float4*>(features)[(size_t)j * 16 + c4];
                const float4 wv = __ldg(reinterpret_cast<const float4*>(weight) + k * 16 + c4);
                acc.x = fmaf(gv.x, wv.x, acc.x);
                acc.y = fmaf(gv.y, wv.y, acc.y);
                acc.z = fmaf(gv.z, wv.z, acc.z);
                acc.w = fmaf(gv.w, wv.w, acc.w);
            }
            // self tap (k = 13)
            acc.x = fmaf(fv.x, w13.x, acc.x);
            acc.y = fmaf(fv.y, w13.y, acc.y);
            acc.z = fmaf(fv.z, w13.z, acc.z);
            acc.w = fmaf(fv.w, w13.w, acc.w);
            // taps 14..26
            while (bhi) {
                const int kb = __ffs(bhi) - 1;
                bhi &= bhi - 1;
                const int k = kb + SELF_K + 1;
                int j;
                if      (cnt == 0) j = (int)info.y;
                else if (cnt == 1) j = (int)info.z;
                else if (cnt == 2) j = (int)info.w;
                else j = pw4 ? __ldg(p32 + (size_t)k * (size_t)n + nn)
                             : (int)__ldg((const long long*)pinp + (size_t)k * (size_t)n + nn);
                cnt++;
                const float4 gv = reinterpret_cast<const float4*>(features)[(size_t)j * 16 + c4];
                const float4 wv = __ldg(reinterpret_cast<const float4*>(weight) + k * 16 + c4);
                acc.x = fmaf(gv.x, wv.x, acc.x);
                acc.y = fmaf(gv.y, wv.y, acc.y);
                acc.z = fmaf(gv.z, wv.z, acc.z);
                acc.w = fmaf(gv.w, wv.w, acc.w);
            }

            __stcs(reinterpret_cast<float4*>(out) + (size_t)nn * 16 + c4, acc);
        }

        if (!hn) break;
        tile = ntile; nn = nn2; v = v2; info = info2; fv = fv2;
    }
}

extern "C" void kernel_launch(void* const* d_in, const int* in_sizes, int n_in,
                              void* d_out, int out_size)
{
    // Inputs in metadata order: features, weight, bias, pair_in, pair_out,
    // pair_mask. Identify by element count; the three 27*N arrays keep their
    // metadata order (pair_in, pair_out, pair_mask).
    int fi = -1, wi = -1, bi = -1;
    int big[3], nbig = 0;
    long long maxc = -1;
    for (int i = 0; i < n_in; i++)
        if ((long long)in_sizes[i] > maxc) { maxc = in_sizes[i]; fi = i; }
    for (int i = 0; i < n_in; i++) {
        if (i == fi) continue;
        if (in_sizes[i] == 64) bi = i;
        else if (in_sizes[i] == KTAPS * CCH) wi = i;
        else if (nbig < 3) big[nbig++] = i;
    }
    const float* features = (const float*)d_in[fi];
    const float* weight   = (const float*)d_in[wi];
    const float* bias     = (const float*)d_in[bi];
    const void*  pinp     = d_in[big[0]];   // pair_in
    // big[1] = pair_out (unused: scatter target == row under mask)
    const void*  maskp    = d_in[big[2]];   // pair_mask
    float* out = (float*)d_out;

    const int n = in_sizes[fi] / CCH;

    kbits<<<(n + 255) / 256, 256>>>(maskp, pinp, n);

    const int ntiles = (n + TILE - 1) / TILE;
    const int grid = ntiles < MAIN_BLOCKS ? ntiles : MAIN_BLOCKS;
    spdwconv_kernel<<<grid, THREADS>>>(features, weight, bias, pinp, out, n);
}